// round 8
// baseline (speedup 1.0000x reference)
#include <cuda_runtime.h>
#include <cuda_bf16.h>
#include <math.h>

#define Bb 8
#define Nn 16384
#define Dd 768
#define Rr 3
#define NE 4
#define NBLK 16384         // proj/out blocks: (B*N)/8 = 131072/8
#define BLK_PER_B 2048     // NBLK / Bb

// Scratch (allocation-free rule: __device__ globals)
__device__ float g_xr[Bb * Rr * Nn];     // (B,R,N): NCHW image (b,r,h,w)
__device__ float g_part[NBLK * Rr];      // per-proj-block partial sums of xr
__device__ float g_G[Bb * NE];
__device__ float g_mixed[Bb * Rr * Nn];  // (B,R,N)

// k_mixall dynamic smem layout (floats):
//   img 16384 | d64 4096 | c64 4096 | d32 1024 | c32 1024 | d16 256 | c16 256
#define SM_FLOATS (16384 + 4096 + 4096 + 1024 + 1024 + 256 + 256)
#define SM_BYTES  (SM_FLOATS * 4)

// ---------------------------------------------------------------------------
// Kernel 1: xr = x @ Wd + bd  (+ per-block partial sums for the mean).
// Warp per row; Wd transposed in smem as float4 (conflict-free LDS.128).
// x read with .cs (evict-first) so scratch stays L2-resident.
// ---------------------------------------------------------------------------
__global__ void k_proj(const float* __restrict__ x,
                       const float* __restrict__ Wd,
                       const float* __restrict__ bd) {
    __shared__ float4 sW[Rr][192];                // sW[r][i] = Wd[(4i..4i+3), r]
    __shared__ float sp[8][3];
    int tid = threadIdx.x;
    for (int idx = tid; idx < Rr * 192; idx += blockDim.x) {
        int r = idx / 192, i = idx - r * 192;
        int d0 = i * 4;
        sW[r][i] = make_float4(Wd[(d0 + 0) * 3 + r], Wd[(d0 + 1) * 3 + r],
                               Wd[(d0 + 2) * 3 + r], Wd[(d0 + 3) * 3 + r]);
    }
    __syncthreads();

    int warp = tid >> 5, lane = tid & 31;
    int row = blockIdx.x * 8 + warp;              // [0, B*N)
    const float4* xr4 = (const float4*)(x + (long long)row * Dd);

    float a0 = 0.f, a1 = 0.f, a2 = 0.f;
#pragma unroll
    for (int k = 0; k < 6; k++) {
        int f4i = lane + 32 * k;                  // 192 float4 per row
        float4 v = __ldcs(xr4 + f4i);
        float4 w0 = sW[0][f4i];
        float4 w1 = sW[1][f4i];
        float4 w2 = sW[2][f4i];
        a0 += v.x * w0.x + v.y * w0.y + v.z * w0.z + v.w * w0.w;
        a1 += v.x * w1.x + v.y * w1.y + v.z * w1.z + v.w * w1.w;
        a2 += v.x * w2.x + v.y * w2.y + v.z * w2.z + v.w * w2.w;
    }
#pragma unroll
    for (int off = 16; off > 0; off >>= 1) {
        a0 += __shfl_down_sync(0xffffffffu, a0, off);
        a1 += __shfl_down_sync(0xffffffffu, a1, off);
        a2 += __shfl_down_sync(0xffffffffu, a2, off);
    }
    if (lane == 0) {
        int b = row >> 14, n = row & (Nn - 1);
        float s0 = a0 + bd[0], s1 = a1 + bd[1], s2 = a2 + bd[2];
        g_xr[((long long)b * Rr + 0) * Nn + n] = s0;
        g_xr[((long long)b * Rr + 1) * Nn + n] = s1;
        g_xr[((long long)b * Rr + 2) * Nn + n] = s2;
        sp[warp][0] = s0; sp[warp][1] = s1; sp[warp][2] = s2;
    }
    __syncthreads();
    if (tid == 0) {
        float p0 = 0.f, p1 = 0.f, p2 = 0.f;
#pragma unroll
        for (int w = 0; w < 8; w++) { p0 += sp[w][0]; p1 += sp[w][1]; p2 += sp[w][2]; }
        g_part[blockIdx.x * 3 + 0] = p0;
        g_part[blockIdx.x * 3 + 1] = p1;
        g_part[blockIdx.x * 3 + 2] = p2;
    }
}

// ---------------------------------------------------------------------------
// Kernel 2: gate.  One block, 256 threads.  Contiguous coalesced reduce of
// g_part in a fixed deterministic order, then top-2 softmax.
// ---------------------------------------------------------------------------
__global__ void k_gate(const float* __restrict__ noise,
                       const float* __restrict__ Wg,
                       const float* __restrict__ Wn) {
    __shared__ float sp[256][3];
    __shared__ float xa[Bb * Rr];
    int t = threadIdx.x;
    // thread t sums proj-blocks [t*64, (t+1)*64) — contiguous 768B read
    const float* p = g_part + t * 64 * 3;
    float s0 = 0.f, s1 = 0.f, s2 = 0.f;
#pragma unroll 8
    for (int i = 0; i < 64; i++) {
        s0 += p[i * 3 + 0]; s1 += p[i * 3 + 1]; s2 += p[i * 3 + 2];
    }
    sp[t][0] = s0; sp[t][1] = s1; sp[t][2] = s2;
    __syncthreads();
    if (t < Bb * Rr) {
        int b = t / Rr, r = t - (t / Rr) * Rr;
        // batch b covers threads [b*32, (b+1)*32): fixed serial order
        float s = 0.f;
#pragma unroll
        for (int k = 0; k < 32; k++) s += sp[b * 32 + k][r];
        xa[t] = s * (1.0f / (float)Nn);
    }
    __syncthreads();
    if (t < Bb) {
        int b = t;
        float xa0 = xa[b * 3 + 0], xa1 = xa[b * 3 + 1], xa2 = xa[b * 3 + 2];
        float hl[NE];
#pragma unroll
        for (int e = 0; e < NE; e++) {
            float hg = xa0 * Wg[0 * NE + e] + xa1 * Wg[1 * NE + e] + xa2 * Wg[2 * NE + e];
            float hn = xa0 * Wn[0 * NE + e] + xa1 * Wn[1 * NE + e] + xa2 * Wn[2 * NE + e];
            float sp2 = (hn > 0.f) ? hn + log1pf(expf(-hn)) : log1pf(expf(hn));
            hl[e] = hg + noise[b * NE + e] * sp2;
        }
        int i1 = 0;
#pragma unroll
        for (int e = 1; e < NE; e++) if (hl[e] > hl[i1]) i1 = e;
        int i2 = -1;
#pragma unroll
        for (int e = 0; e < NE; e++) {
            if (e == i1) continue;
            if (i2 < 0 || hl[e] > hl[i2]) i2 = e;
        }
        float e2 = expf(hl[i2] - hl[i1]);
        float inv = 1.0f / (1.0f + e2);
        float g[NE] = {0.f, 0.f, 0.f, 0.f};
        g[i1] = inv;
        g[i2] = e2 * inv;
#pragma unroll
        for (int e = 0; e < NE; e++) g_G[b * NE + e] = g[e];
    }
}

// ---------------------------------------------------------------------------
// Kernel 3: whole expert pipeline per (b,r) image, entirely in smem.
// 24 blocks x 1024 threads, ~107KB dynamic smem.
// ---------------------------------------------------------------------------
__global__ void k_mixall(const float* __restrict__ dwk,
                         const float* __restrict__ dwb) {
    extern __shared__ float sm[];
    float* img = sm;                 // 16384
    float* d64 = img + 16384;        // 4096
    float* c64 = d64 + 4096;         // 4096
    float* d32 = c64 + 4096;         // 1024
    float* c32 = d32 + 1024;         // 1024
    float* d16 = c32 + 1024;         // 256
    float* c16 = d16 + 256;          // 256

    int br = blockIdx.x;
    int b = br / Rr, r = br - b * Rr;
    const float* gimg = g_xr + (long long)br * Nn;
    float* outp = g_mixed + (long long)br * Nn;
    int t = threadIdx.x;             // 0..1023

    float k9[9];
#pragma unroll
    for (int i = 0; i < 9; i++) k9[i] = __ldg(dwk + r * 9 + i);
    float kb = __ldg(dwb + r);

    // load full image (coalesced float4)
    {
        float4* i4 = (float4*)img;
        const float4* g4 = (const float4*)gimg;
        for (int i = t; i < 4096; i += 1024) i4[i] = g4[i];
    }
    __syncthreads();

    // downsamples (half-pixel average positions)
    for (int i = t; i < 4096; i += 1024) {
        int y = i >> 6, x = i & 63;
        const float* p0 = img + (2 * y) * 128 + 2 * x;
        d64[i] = 0.25f * (p0[0] + p0[1] + p0[128] + p0[129]);
    }
    for (int i = t; i < 1024; i += 1024) {
        int y = i >> 5, x = i & 31;
        const float* p0 = img + (4 * y + 1) * 128 + 4 * x + 1;
        d32[i] = 0.25f * (p0[0] + p0[1] + p0[128] + p0[129]);
    }
    if (t < 256) {
        int y = t >> 4, x = t & 15;
        const float* p0 = img + (8 * y + 3) * 128 + 8 * x + 3;
        d16[t] = 0.25f * (p0[0] + p0[1] + p0[128] + p0[129]);
    }
    __syncthreads();

    // small-scale convs (zero padding)
#pragma unroll 1
    for (int i = t; i < 4096; i += 1024) {
        int y = i >> 6, x = i & 63;
        float v = kb;
#pragma unroll
        for (int ky = 0; ky < 3; ky++) {
            int yy = y + ky - 1;
            if (yy < 0 || yy >= 64) continue;
#pragma unroll
            for (int kx = 0; kx < 3; kx++) {
                int xx = x + kx - 1;
                if (xx < 0 || xx >= 64) continue;
                v += d64[yy * 64 + xx] * k9[ky * 3 + kx];
            }
        }
        c64[i] = v;
    }
    for (int i = t; i < 1024; i += 1024) {
        int y = i >> 5, x = i & 31;
        float v = kb;
#pragma unroll
        for (int ky = 0; ky < 3; ky++) {
            int yy = y + ky - 1;
            if (yy < 0 || yy >= 32) continue;
#pragma unroll
            for (int kx = 0; kx < 3; kx++) {
                int xx = x + kx - 1;
                if (xx < 0 || xx >= 32) continue;
                v += d32[yy * 32 + xx] * k9[ky * 3 + kx];
            }
        }
        c32[i] = v;
    }
    if (t < 256) {
        int y = t >> 4, x = t & 15;
        float v = kb;
#pragma unroll
        for (int ky = 0; ky < 3; ky++) {
            int yy = y + ky - 1;
            if (yy < 0 || yy >= 16) continue;
#pragma unroll
            for (int kx = 0; kx < 3; kx++) {
                int xx = x + kx - 1;
                if (xx < 0 || xx >= 16) continue;
                v += d16[yy * 16 + xx] * k9[ky * 3 + kx];
            }
        }
        c16[t] = v;
    }
    __syncthreads();

    float G0 = g_G[b * NE + 0], G1 = g_G[b * NE + 1];
    float G2 = g_G[b * NE + 2], G3 = g_G[b * NE + 3];

    // full-res conv + bilinear upsamples + gated mix (all smem)
    for (int i = t; i < Nn; i += 1024) {
        int y = i >> 7, x = i & 127;
        float v = kb;
#pragma unroll
        for (int ky = 0; ky < 3; ky++) {
            int yy = y + ky - 1;
            if (yy < 0 || yy >= 128) continue;
#pragma unroll
            for (int kx = 0; kx < 3; kx++) {
                int xx = x + kx - 1;
                if (xx < 0 || xx >= 128) continue;
                v += img[yy * 128 + xx] * k9[ky * 3 + kx];
            }
        }
        // up from c64 (scale 0.5): pos = 0.5*y - 0.25
        float u1, u2, u3;
        {
            float py = 0.5f * y - 0.25f, px = 0.5f * x - 0.25f;
            float fy = floorf(py), fx = floorf(px);
            float wy = py - fy, wx = px - fx;
            int y0 = max(0, min(63, (int)fy)), y1 = max(0, min(63, (int)fy + 1));
            int x0 = max(0, min(63, (int)fx)), x1 = max(0, min(63, (int)fx + 1));
            float v00 = c64[y0 * 64 + x0], v01 = c64[y0 * 64 + x1];
            float v10 = c64[y1 * 64 + x0], v11 = c64[y1 * 64 + x1];
            u1 = (v00 + wx * (v01 - v00)) + wy * ((v10 + wx * (v11 - v10)) - (v00 + wx * (v01 - v00)));
        }
        {
            float py = 0.25f * y - 0.375f, px = 0.25f * x - 0.375f;
            float fy = floorf(py), fx = floorf(px);
            float wy = py - fy, wx = px - fx;
            int y0 = max(0, min(31, (int)fy)), y1 = max(0, min(31, (int)fy + 1));
            int x0 = max(0, min(31, (int)fx)), x1 = max(0, min(31, (int)fx + 1));
            float v00 = c32[y0 * 32 + x0], v01 = c32[y0 * 32 + x1];
            float v10 = c32[y1 * 32 + x0], v11 = c32[y1 * 32 + x1];
            u2 = (v00 + wx * (v01 - v00)) + wy * ((v10 + wx * (v11 - v10)) - (v00 + wx * (v01 - v00)));
        }
        {
            float py = 0.125f * y - 0.4375f, px = 0.125f * x - 0.4375f;
            float fy = floorf(py), fx = floorf(px);
            float wy = py - fy, wx = px - fx;
            int y0 = max(0, min(15, (int)fy)), y1 = max(0, min(15, (int)fy + 1));
            int x0 = max(0, min(15, (int)fx)), x1 = max(0, min(15, (int)fx + 1));
            float v00 = c16[y0 * 16 + x0], v01 = c16[y0 * 16 + x1];
            float v10 = c16[y1 * 16 + x0], v11 = c16[y1 * 16 + x1];
            u3 = (v00 + wx * (v01 - v00)) + wy * ((v10 + wx * (v11 - v10)) - (v00 + wx * (v01 - v00)));
        }
        outp[i] = G0 * v + G1 * u1 + G2 * u2 + G3 * u3;
    }
}

// ---------------------------------------------------------------------------
// Kernel 4: out = x + mixed @ Wu + bu.  Streaming loads/stores for x/out.
// ---------------------------------------------------------------------------
__global__ void k_out(const float* __restrict__ x,
                      const float* __restrict__ Wu,
                      const float* __restrict__ bu,
                      float* __restrict__ out) {
    int t = threadIdx.x;  // 0..191
    const float4* Wu4 = (const float4*)Wu;
    float4 w0 = Wu4[t], w1 = Wu4[192 + t], w2 = Wu4[384 + t];
    float4 bv = ((const float4*)bu)[t];

    long long row0 = (long long)blockIdx.x * 8;
#pragma unroll
    for (int i = 0; i < 8; i++) {
        long long row = row0 + i;
        int b = (int)(row >> 14), n = (int)(row & (Nn - 1));
        float m0 = g_mixed[((long long)b * Rr + 0) * Nn + n];
        float m1 = g_mixed[((long long)b * Rr + 1) * Nn + n];
        float m2 = g_mixed[((long long)b * Rr + 2) * Nn + n];
        float4 xv = __ldcs(((const float4*)(x + row * Dd)) + t);
        float4 rv;
        rv.x = xv.x + m0 * w0.x + m1 * w1.x + m2 * w2.x + bv.x;
        rv.y = xv.y + m0 * w0.y + m1 * w1.y + m2 * w2.y + bv.y;
        rv.z = xv.z + m0 * w0.z + m1 * w1.z + m2 * w2.z + bv.z;
        rv.w = xv.w + m0 * w0.w + m1 * w1.w + m2 * w2.w + bv.w;
        __stcs(((float4*)out) + row * 192 + t, rv);
    }
}

// ---------------------------------------------------------------------------
extern "C" void kernel_launch(void* const* d_in, const int* in_sizes, int n_in,
                              void* d_out, int out_size) {
    const float* x     = (const float*)d_in[0];
    const float* noise = (const float*)d_in[1];
    const float* Wd    = (const float*)d_in[2];
    const float* bd    = (const float*)d_in[3];
    const float* Wu    = (const float*)d_in[4];
    const float* bu    = (const float*)d_in[5];
    const float* Wg    = (const float*)d_in[6];
    const float* Wn    = (const float*)d_in[7];
    const float* dwk   = (const float*)d_in[8];
    const float* dwb   = (const float*)d_in[9];
    float* out = (float*)d_out;

    static bool attr_set = false;
    if (!attr_set) {
        cudaFuncSetAttribute(k_mixall,
                             cudaFuncAttributeMaxDynamicSharedMemorySize, SM_BYTES);
        attr_set = true;
    }

    k_proj<<<NBLK, 256>>>(x, Wd, bd);
    k_gate<<<1, 256>>>(noise, Wg, Wn);
    k_mixall<<<Bb * Rr, 1024, SM_BYTES>>>(dwk, dwb);
    k_out<<<NBLK, 192>>>(x, Wu, bu, out);
}